// round 10
// baseline (speedup 1.0000x reference)
#include <cuda_runtime.h>
#include <math.h>
#include <stdint.h>

#define N 512
#define C 157
#define M 20
#define NC (N*C)
#define SIGMA2_INV (1.0f/(2.0f*300.0f*300.0f))
#define EPSV 1e-7f
#define INV_DECAY (1.0f/0.9f)
#define LOG2_INV_DECAY 0.15200309344504997f   /* log2(1/0.9) */
#define RPAD 33                                /* rowpart pitch (conflict-free) */
#define NW 12                                  /* warps per CTA */
#define NT (NW*32)                             /* 384 threads */

__device__ float g_partial[N];
__device__ unsigned int g_count = 0;

__global__ __launch_bounds__(NT, 4) void fused_kernel(
    const float* __restrict__ a, const float* __restrict__ aa,
    const float* __restrict__ target, const float* __restrict__ bank_values,
    const int* __restrict__ bank_times, const int* __restrict__ bank_mask,
    const int* __restrict__ ids, const int* __restrict__ times,
    float* __restrict__ out, int out_size)
{
    __shared__ float msg_s[C], fmsg_s[C];
    __shared__ float rowpart[C * RPAD];     // [row][lane]
    __shared__ float colpart[NW][160];      // per-warp col partials
    __shared__ float wpast[M], wfut[M];
    __shared__ float denp_s, denf_s;
    __shared__ float wsum[NW];
    __shared__ int last_s;

    const int n = blockIdx.x;
    const int t = threadIdx.x;
    const int w = t >> 5;
    const int l = t & 31;
    const int id = ids[n];
    const float* aa_g = aa + (size_t)n * (C*C);

    // ---- prefetch bank_values row + a/target into registers (before any barrier) ----
    float v[M];
    float av = 0.f, tg = 0.f;
    if (t < C) {
        const float* vals = bank_values + (size_t)id * (M*C);
        #pragma unroll
        for (int m = 0; m < M; m++) v[m] = vals[m*C + t];
        av = a[n*C + t];
        tg = target[n*C + t];
    }

    // ---- temporal weights: warp 0, ballot-rank ----
    if (t < 32) {
        const bool vd = l < M;
        int tsi = 0, mk = 0;
        if (vd) { tsi = bank_times[id*M + l]; mk = bank_mask[id*M + l]; }
        const float t0 = (float)times[n];
        float ts = (float)tsi;
        float d = ts - t0;
        float kern = __expf(-d*d*SIGMA2_INV);
        bool condp = vd && mk && (ts < t0);
        bool condf = vd && mk && (ts > t0);
        unsigned bp = __ballot_sync(0xFFFFFFFFu, condp);
        unsigned bf = __ballot_sync(0xFFFFFFFFu, condf);
        unsigned below = (1u << l) - 1u;
        float dwp = condp ? exp2f(LOG2_INV_DECAY * (float)__popc(bp & below)) : 0.f;
        float dwf = condf ? exp2f(LOG2_INV_DECAY * (float)__popc(bf & below)) : 0.f;
        if (vd) { wpast[l] = dwp * kern; wfut[l] = dwf * kern; }
        if (l == 0) {
            float cp_ = (float)__popc(bp), cf_ = (float)__popc(bf);
            denp_s = (exp2f(LOG2_INV_DECAY * cp_) - 1.f) / (INV_DECAY - 1.f);
            denf_s = (exp2f(LOG2_INV_DECAY * cf_) - 1.f) / (INV_DECAY - 1.f);
        }
    }
    __syncthreads();

    // ---- msg/fmsg from registers (no LDG behind this barrier) ----
    if (t < C) {
        float nump = 0.f, numf = 0.f;
        #pragma unroll
        for (int m = 0; m < M; m++) {
            nump = fmaf(wpast[m], v[m], nump);
            numf = fmaf(wfut[m],  v[m], numf);
        }
        float denp = denp_s, denf = denf_s;
        msg_s[t]  = (denp > 0.f) ? nump / fmaxf(denp, EPSV) : 0.f;
        fmsg_s[t] = (denf > 0.f) ? numf / fmaxf(denf, EPSV) : 0.f;
    }
    __syncthreads();

    // ---- single streaming pass over aa, LDG.128 with per-warp alignment shift ----
    // float index of row i start = n*24649 + i*157 ≡ (n+i) (mod 4); rows of warp w
    // are i = w+12r so (n+i)%4 == (n+w)%4 is warp-constant. shift s4 makes
    // (row base + s4 floats) 16B-aligned for every row this warp touches.
    // lane l covers cols {s4+4l..s4+4l+3} (float4) + tails: col l (l<s4) and
    // col s4+128+l (l<29-s4). Coverage of [0,157) exact and disjoint.
    const int s4 = (4 - ((n + w) & 3)) & 3;
    const bool hok = (l < s4);
    const bool eok = (l < 29 - s4);
    const int je = s4 + 128 + l;
    float f0 = fmsg_s[s4 + 4*l + 0];
    float f1 = fmsg_s[s4 + 4*l + 1];
    float f2 = fmsg_s[s4 + 4*l + 2];
    float f3 = fmsg_s[s4 + 4*l + 3];
    float fh = hok ? fmsg_s[l]  : 0.f;
    float fe = eok ? fmsg_s[je] : 0.f;
    float c0 = 0.f, c1 = 0.f, c2 = 0.f, c3 = 0.f, ch = 0.f, ce = 0.f;

    #pragma unroll 3
    for (int r = 0; r < 14; r++) {
        int i = w + NW*r;
        if (i < C) {
            const float* rp = aa_g + i*C;
            float4 v4 = *(const float4*)(rp + s4 + 4*l);
            float vh = hok ? rp[l]  : 0.f;
            float ve = eok ? rp[je] : 0.f;
            float mi = msg_s[i];                 // broadcast LDS
            c0 = fmaf(v4.x, mi, c0);
            c1 = fmaf(v4.y, mi, c1);
            c2 = fmaf(v4.z, mi, c2);
            c3 = fmaf(v4.w, mi, c3);
            ch = fmaf(vh,   mi, ch);
            ce = fmaf(ve,   mi, ce);
            float rs = fmaf(v4.x, f0, v4.y*f1) + fmaf(v4.z, f2, v4.w*f3)
                     + fmaf(vh, fh, ve*fe);
            rowpart[i*RPAD + l] = rs;
        }
    }
    // scatter col partials (disjoint columns per lane within the warp)
    colpart[w][s4 + 4*l + 0] = c0;
    colpart[w][s4 + 4*l + 1] = c1;
    colpart[w][s4 + 4*l + 2] = c2;
    colpart[w][s4 + 4*l + 3] = c3;
    if (hok) colpart[w][l]  = ch;
    if (eok) colpart[w][je] = ce;
    __syncthreads();

    // ---- epilogue: fold partials, qa, fused double-BCE (fast-math) ----
    float s = 0.f;
    if (t < C) {
        float col = 0.f;
        #pragma unroll
        for (int ww = 0; ww < NW; ww++) col += colpart[ww][t];
        float r0 = 0.f, r1 = 0.f, r2 = 0.f, r3 = 0.f;
        const float* rp = rowpart + t*RPAD;
        #pragma unroll
        for (int j = 0; j < 32; j += 4) {
            r0 += rp[j]; r1 += rp[j+1]; r2 += rp[j+2]; r3 += rp[j+3];
        }
        float x = av + col + ((r0 + r1) + (r2 + r3));
        float qa = 1.f / (1.f + __expf(-x));
        out[n*C + t] = qa;
        float p1 = fminf(fmaxf(qa, EPSV), 1.f - EPSV);
        s  = tg*__logf(p1) + (1.f - tg)*__logf(1.f - p1);
        float p2 = 1.f / (1.f + __expf(-av));
        p2 = fminf(fmaxf(p2, EPSV), 1.f - EPSV);
        s += tg*__logf(p2) + (1.f - tg)*__logf(1.f - p2);
    }
    #pragma unroll
    for (int off = 16; off > 0; off >>= 1)
        s += __shfl_xor_sync(0xFFFFFFFFu, s, off);
    if (l == 0) wsum[w] = s;
    __syncthreads();
    if (t == 0) {
        float bs = 0.f;
        #pragma unroll
        for (int ww = 0; ww < NW; ww++) bs += wsum[ww];
        g_partial[n] = bs;
        __threadfence();
        unsigned old = atomicAdd(&g_count, 1u);
        last_s = (old == N - 1);
    }
    __syncthreads();

    // ---- last CTA folds the 512 partials (deterministic fixed order) ----
    if (last_s) {
        float ps = 0.f;
        if (t < 128)
            ps = (g_partial[t] + g_partial[t + 128])
               + (g_partial[t + 256] + g_partial[t + 384]);
        #pragma unroll
        for (int off = 16; off > 0; off >>= 1)
            ps += __shfl_xor_sync(0xFFFFFFFFu, ps, off);
        if (l == 0) wsum[w] = ps;
        __syncthreads();
        if (t == 0) {
            float tot = ((wsum[0] + wsum[1]) + (wsum[2] + wsum[3]));
            if (out_size > NC) out[NC] = -tot / (3.0f * (float)NC);
            g_count = 0;        // reset for next graph replay
        }
    }
}

extern "C" void kernel_launch(void* const* d_in, const int* in_sizes, int n_in,
                              void* d_out, int out_size) {
    const float* a           = (const float*)d_in[0];
    const float* aa          = (const float*)d_in[1];
    const float* target      = (const float*)d_in[2];
    const float* bank_values = (const float*)d_in[3];
    const int*   bank_times  = (const int*)d_in[4];
    const int*   bank_mask   = (const int*)d_in[5];
    const int*   ids         = (const int*)d_in[6];
    const int*   times       = (const int*)d_in[7];
    float* out = (float*)d_out;

    fused_kernel<<<N, NT>>>(a, aa, target, bank_values, bank_times,
                            bank_mask, ids, times, out, out_size);
}

// round 11
// speedup vs baseline: 1.1544x; 1.1544x over previous
#include <cuda_runtime.h>
#include <math.h>

#define N 512
#define C 157
#define M 20
#define NC (N*C)
#define SIGMA2_INV (1.0f/(2.0f*300.0f*300.0f))
#define EPSV 1e-7f
#define INV_DECAY (1.0f/0.9f)
#define LOG2_INV_DECAY 0.15200309344504997f   /* log2(1/0.9) */
#define RPAD 33                                /* rowpart pitch (conflict-free) */
#define NW 12                                  /* warps per CTA */
#define NT (NW*32)                             /* 384 threads */

__device__ float g_partial[N];
__device__ unsigned int g_count = 0;

__global__ __launch_bounds__(NT, 4) void fused_kernel(
    const float* __restrict__ a, const float* __restrict__ aa,
    const float* __restrict__ target, const float* __restrict__ bank_values,
    const int* __restrict__ bank_times, const int* __restrict__ bank_mask,
    const int* __restrict__ ids, const int* __restrict__ times,
    float* __restrict__ out, int out_size)
{
    __shared__ float msg_s[C], fmsg_s[C];
    __shared__ float rowpart[C * RPAD];     // [row][lane]
    __shared__ float colpart[NW][160];      // per-warp col partials
    __shared__ float wpast[M], wfut[M];
    __shared__ float denp_s, denf_s;
    __shared__ float wsum[NW];
    __shared__ int last_s;

    const int n = blockIdx.x;
    const int t = threadIdx.x;
    const int w = t >> 5;
    const int l = t & 31;
    const int id = ids[n];
    const float* aa_g = aa + (size_t)n * (C*C);

    // ---- prefetch bank_values row + a/target into registers (before any barrier) ----
    float v[M];
    float av = 0.f, tg = 0.f;
    if (t < C) {
        const float* vals = bank_values + (size_t)id * (M*C);
        #pragma unroll
        for (int m = 0; m < M; m++) v[m] = vals[m*C + t];
        av = a[n*C + t];
        tg = target[n*C + t];
    }

    // ---- temporal weights: warp 0, ballot-rank ----
    if (t < 32) {
        const bool vd = l < M;
        int tsi = 0, mk = 0;
        if (vd) { tsi = bank_times[id*M + l]; mk = bank_mask[id*M + l]; }
        const float t0 = (float)times[n];
        float ts = (float)tsi;
        float d = ts - t0;
        float kern = __expf(-d*d*SIGMA2_INV);
        bool condp = vd && mk && (ts < t0);
        bool condf = vd && mk && (ts > t0);
        unsigned bp = __ballot_sync(0xFFFFFFFFu, condp);
        unsigned bf = __ballot_sync(0xFFFFFFFFu, condf);
        unsigned below = (1u << l) - 1u;
        float dwp = condp ? exp2f(LOG2_INV_DECAY * (float)__popc(bp & below)) : 0.f;
        float dwf = condf ? exp2f(LOG2_INV_DECAY * (float)__popc(bf & below)) : 0.f;
        if (vd) { wpast[l] = dwp * kern; wfut[l] = dwf * kern; }
        if (l == 0) {
            float cp_ = (float)__popc(bp), cf_ = (float)__popc(bf);
            denp_s = (exp2f(LOG2_INV_DECAY * cp_) - 1.f) / (INV_DECAY - 1.f);
            denf_s = (exp2f(LOG2_INV_DECAY * cf_) - 1.f) / (INV_DECAY - 1.f);
        }
    }
    __syncthreads();

    // ---- msg/fmsg from registers (no LDG behind this barrier) ----
    if (t < C) {
        float nump = 0.f, numf = 0.f;
        #pragma unroll
        for (int m = 0; m < M; m++) {
            nump = fmaf(wpast[m], v[m], nump);
            numf = fmaf(wfut[m],  v[m], numf);
        }
        float denp = denp_s, denf = denf_s;
        msg_s[t]  = (denp > 0.f) ? nump / fmaxf(denp, EPSV) : 0.f;
        fmsg_s[t] = (denf > 0.f) ? numf / fmaxf(denf, EPSV) : 0.f;
    }
    __syncthreads();

    // ---- single streaming pass over aa; scalar LDG.32 with streaming hint ----
    // lane l owns cols j = l+32q (q<5); warp w owns rows i = w+NW*r.
    const bool q4ok = (l + 128) < C;
    float fm0 = fmsg_s[l];
    float fm1 = fmsg_s[l + 32];
    float fm2 = fmsg_s[l + 64];
    float fm3 = fmsg_s[l + 96];
    float fm4 = q4ok ? fmsg_s[l + 128] : 0.f;
    float c0 = 0.f, c1 = 0.f, c2 = 0.f, c3 = 0.f, c4 = 0.f;

    #pragma unroll 2
    for (int r = 0; r < 14; r++) {
        int i = w + NW*r;
        if (i < C) {
            const float* rp = aa_g + i*C;
            float v0 = __ldcs(rp + l);
            float v1 = __ldcs(rp + l + 32);
            float v2 = __ldcs(rp + l + 64);
            float v3 = __ldcs(rp + l + 96);
            float v4 = q4ok ? __ldcs(rp + l + 128) : 0.f;
            float mi = msg_s[i];                 // broadcast LDS
            c0 = fmaf(v0, mi, c0);
            c1 = fmaf(v1, mi, c1);
            c2 = fmaf(v2, mi, c2);
            c3 = fmaf(v3, mi, c3);
            c4 = fmaf(v4, mi, c4);
            float rs = fmaf(v0, fm0, v1*fm1) + fmaf(v2, fm2, v3*fm3) + v4*fm4;
            rowpart[i*RPAD + l] = rs;
        }
    }
    colpart[w][l]       = c0;
    colpart[w][l + 32]  = c1;
    colpart[w][l + 64]  = c2;
    colpart[w][l + 96]  = c3;
    if (q4ok) colpart[w][l + 128] = c4;
    __syncthreads();

    // ---- epilogue: fold partials, qa, fused double-BCE (fast-math) ----
    float s = 0.f;
    if (t < C) {
        float col = 0.f;
        #pragma unroll
        for (int ww = 0; ww < NW; ww++) col += colpart[ww][t];
        float r0 = 0.f, r1 = 0.f, r2 = 0.f, r3 = 0.f;
        const float* rp = rowpart + t*RPAD;
        #pragma unroll
        for (int j = 0; j < 32; j += 4) {
            r0 += rp[j]; r1 += rp[j+1]; r2 += rp[j+2]; r3 += rp[j+3];
        }
        float x = av + col + ((r0 + r1) + (r2 + r3));
        float qa = 1.f / (1.f + __expf(-x));
        __stcs(out + n*C + t, qa);
        float p1 = fminf(fmaxf(qa, EPSV), 1.f - EPSV);
        s  = tg*__logf(p1) + (1.f - tg)*__logf(1.f - p1);
        float p2 = 1.f / (1.f + __expf(-av));
        p2 = fminf(fmaxf(p2, EPSV), 1.f - EPSV);
        s += tg*__logf(p2) + (1.f - tg)*__logf(1.f - p2);
    }
    #pragma unroll
    for (int off = 16; off > 0; off >>= 1)
        s += __shfl_xor_sync(0xFFFFFFFFu, s, off);
    if (l == 0) wsum[w] = s;
    __syncthreads();
    if (t == 0) {
        float bs = 0.f;
        #pragma unroll
        for (int ww = 0; ww < NW; ww++) bs += wsum[ww];
        g_partial[n] = bs;
        __threadfence();
        unsigned old = atomicAdd(&g_count, 1u);
        last_s = (old == N - 1);
    }
    __syncthreads();

    // ---- last CTA folds the 512 partials (deterministic fixed order) ----
    if (last_s) {
        float ps = 0.f;
        if (t < 128)
            ps = (g_partial[t] + g_partial[t + 128])
               + (g_partial[t + 256] + g_partial[t + 384]);
        #pragma unroll
        for (int off = 16; off > 0; off >>= 1)
            ps += __shfl_xor_sync(0xFFFFFFFFu, ps, off);
        if (l == 0) wsum[w] = ps;
        __syncthreads();
        if (t == 0) {
            float tot = ((wsum[0] + wsum[1]) + (wsum[2] + wsum[3]));
            if (out_size > NC) out[NC] = -tot / (3.0f * (float)NC);
            g_count = 0;        // reset for next graph replay
        }
    }
}

extern "C" void kernel_launch(void* const* d_in, const int* in_sizes, int n_in,
                              void* d_out, int out_size) {
    const float* a           = (const float*)d_in[0];
    const float* aa          = (const float*)d_in[1];
    const float* target      = (const float*)d_in[2];
    const float* bank_values = (const float*)d_in[3];
    const int*   bank_times  = (const int*)d_in[4];
    const int*   bank_mask   = (const int*)d_in[5];
    const int*   ids         = (const int*)d_in[6];
    const int*   times       = (const int*)d_in[7];
    float* out = (float*)d_out;

    fused_kernel<<<N, NT>>>(a, aa, target, bank_values, bank_times,
                            bank_mask, ids, times, out, out_size);
}